// round 2
// baseline (speedup 1.0000x reference)
#include <cuda_runtime.h>

namespace {

constexpr int G = 8;     // group size
constexpr int L = 50;    // history length
constexpr int S = 32;    // social neighbors
constexpr int D = 64;    // embed dim
constexpr int A = 16;    // attention dim
constexpr int NR = 5;    // num ratings

// mask dtype kind: 0 = uint8, 1 = int32, 2 = float32
__device__ int g_mask_kind;

__global__ void detect_mask_kind(const unsigned int* __restrict__ m, int n_words)
{
    __shared__ int s_not_i32, s_not_f32;
    if (threadIdx.x == 0) { s_not_i32 = 0; s_not_f32 = 0; }
    __syncthreads();
    int ni = 0, nf = 0;
    for (int i = threadIdx.x; i < n_words; i += blockDim.x) {
        unsigned int v = m[i];
        if (v > 1u) ni = 1;
        if (v != 0u && v != 0x3F800000u) nf = 1;
    }
    if (ni) s_not_i32 = 1;
    if (nf) s_not_f32 = 1;
    __syncthreads();
    if (threadIdx.x == 0)
        g_mask_kind = (!s_not_i32) ? 1 : ((!s_not_f32) ? 2 : 0);
}

__device__ __forceinline__ bool mask_at(const void* m, int idx, int kind)
{
    if (kind == 1) return ((const int*)m)[idx] != 0;
    if (kind == 2) return ((const float*)m)[idx] != 0.f;
    return ((const unsigned char*)m)[idx] != 0;
}

__global__ __launch_bounds__(128)
void enc_kernel(const int* __restrict__ nodes,
                const int* __restrict__ hist_u,
                const int* __restrict__ hist_r,
                const void* __restrict__ hist_m,
                const int* __restrict__ soc_a,
                const void* __restrict__ soc_m,
                const float* __restrict__ features,
                const float* __restrict__ r_embed,
                const float* __restrict__ wg1,
                const float* __restrict__ bg1,
                const float* __restrict__ wg2,
                const float* __restrict__ bg2,
                const float* __restrict__ w1,
                const float* __restrict__ b1,
                float* __restrict__ out)
{
    __shared__ float s_mem[G][D + 1];   // member embeddings (padded)
    __shared__ float s_wg1[D][A];       // staged wg1
    __shared__ float s_remb[NR][D];     // staged rating embeddings
    __shared__ float s_logit[G];
    __shared__ float s_comb[2 * D];     // [self_feats | neigh_feats]
    __shared__ float s_partA[2][D];     // half-reductions (hist, then GEMM)
    __shared__ float s_partB[2][D];     // half-reductions (social)
    __shared__ int   s_hu[L], s_hr[L], s_su[S];
    __shared__ int   s_hn, s_sn;
    __shared__ int   s_idx[G];

    const int b    = blockIdx.x;
    const int tid  = threadIdx.x;
    const int kind = g_mask_kind;

    if (tid == 0) { s_hn = 0; s_sn = 0; }
    if (tid < G)  s_idx[tid] = nodes[b * G + tid];
    __syncthreads();

    // ---- stage small weights + member rows, compact masked index lists ----
    for (int i = tid; i < D * A; i += 128)
        s_wg1[i / A][i % A] = wg1[i];
    for (int i = tid; i < NR * D; i += 128)
        s_remb[i / D][i % D] = r_embed[i];
    for (int i = tid; i < G * D; i += 128) {
        int g = i >> 6, d0 = i & 63;
        s_mem[g][d0] = features[s_idx[g] * D + d0];
    }
    if (tid < L) {
        if (mask_at(hist_m, b * L + tid, kind)) {
            int p = atomicAdd(&s_hn, 1);
            s_hu[p] = hist_u[b * L + tid];
            s_hr[p] = hist_r[b * L + tid];
        }
    }
    if (tid >= 64 && tid < 64 + S) {
        int j = tid - 64;
        if (mask_at(soc_m, b * S + j, kind)) {
            int p = atomicAdd(&s_sn, 1);
            s_su[p] = soc_a[b * S + j];
        }
    }
    __syncthreads();

    const int hn = s_hn;
    const int sn = s_sn;
    const int half = tid >> 6;   // 0 or 1
    const int d    = tid & 63;

    // ---- attention logits: tid -> (g, a), 16 lanes per group ----
    {
        int g = tid >> 4, a = tid & 15;
        float acc = bg1[a];
        #pragma unroll
        for (int k = 0; k < D; ++k)
            acc += s_mem[g][k] * s_wg1[k][a];
        float lg = tanhf(acc) * wg2[a];
        #pragma unroll
        for (int off = 8; off; off >>= 1)
            lg += __shfl_down_sync(0xffffffffu, lg, off, 16);
        if (a == 0) s_logit[g] = lg + bg2[0];
    }
    __syncthreads();

    // ---- softmax + weighted member sum -> self_feats (threads 0..63) ----
    if (tid < D) {
        float mx = s_logit[0];
        #pragma unroll
        for (int g2 = 1; g2 < G; ++g2) mx = fmaxf(mx, s_logit[g2]);
        float e[G];
        float sum = 0.f;
        #pragma unroll
        for (int g2 = 0; g2 < G; ++g2) { e[g2] = __expf(s_logit[g2] - mx); sum += e[g2]; }
        float inv = 1.f / sum;
        float sf = 0.f;
        #pragma unroll
        for (int g2 = 0; g2 < G; ++g2) sf += e[g2] * inv * s_mem[g2][tid];
        s_comb[tid] = sf;
    }

    // ---- history aggregation: 2 list entries in flight, 64 lanes over D ----
    {
        float acc = 0.f;
        #pragma unroll 4
        for (int l = half; l < hn; l += 2)
            acc += features[s_hu[l] * D + d] + s_remb[s_hr[l]][d];
        s_partA[half][d] = acc;
    }
    // ---- social aggregation ----
    {
        float acc = 0.f;
        #pragma unroll 4
        for (int l = half; l < sn; l += 2)
            acc += features[s_su[l] * D + d];
        s_partB[half][d] = acc;
    }
    __syncthreads();

    if (tid < D) {
        float hm = (s_partA[0][d] + s_partA[1][d]) / fmaxf((float)hn, 1.f);
        float sm = (s_partB[0][d] + s_partB[1][d]) / fmaxf((float)sn, 1.f);
        s_comb[D + d] = 0.5f * (hm + sm);
    }
    __syncthreads();

    // ---- final linear: out[d] = relu(sum_k comb[k] * w1[k][d] + b1[d]) ----
    {
        float acc = 0.f;
        const float* w1h = w1 + half * D * D;
        const float* ch  = s_comb + half * D;
        #pragma unroll 8
        for (int k = 0; k < D; ++k)
            acc += ch[k] * w1h[k * D + d];
        s_partA[half][d] = acc;
    }
    __syncthreads();

    if (tid < D)
        out[b * D + d] = fmaxf(s_partA[0][d] + s_partA[1][d] + b1[d], 0.f);
}

} // namespace

extern "C" void kernel_launch(void* const* d_in, const int* in_sizes, int n_in,
                              void* d_out, int out_size)
{
    const int*   nodes    = (const int*)d_in[0];
    const int*   hist_u   = (const int*)d_in[1];
    const int*   hist_r   = (const int*)d_in[2];
    const void*  hist_m   = d_in[3];
    const int*   soc_a    = (const int*)d_in[4];
    const void*  soc_m    = d_in[5];
    const float* features = (const float*)d_in[6];
    const float* r_embed  = (const float*)d_in[7];
    const float* wg1      = (const float*)d_in[8];
    const float* bg1      = (const float*)d_in[9];
    const float* wg2      = (const float*)d_in[10];
    const float* bg2      = (const float*)d_in[11];
    const float* w1       = (const float*)d_in[12];
    const float* b1       = (const float*)d_in[13];
    float*       out      = (float*)d_out;

    const int B = in_sizes[0] / G;

    // Probe mask dtype from history_mask: sample 2048 32-bit words.
    // (Safe even if masks are 1 byte each: in_sizes[3] = B*L >= 4*2048 bytes.)
    int n_words = in_sizes[3] / 4;
    if (n_words > 2048) n_words = 2048;
    detect_mask_kind<<<1, 256>>>((const unsigned int*)hist_m, n_words);

    enc_kernel<<<B, 128>>>(nodes, hist_u, hist_r, hist_m, soc_a, soc_m,
                           features, r_embed, wg1, bg1, wg2, bg2, w1, b1, out);
}

// round 3
// speedup vs baseline: 1.1755x; 1.1755x over previous
#include <cuda_runtime.h>

namespace {

constexpr int G  = 8;    // group size
constexpr int L  = 50;   // history length
constexpr int S  = 32;   // social neighbors
constexpr int D  = 64;   // embed dim
constexpr int A  = 16;   // attention dim
constexpr int NR = 5;    // num ratings
constexpr int R  = 4;    // batch rows per CTA
constexpr int NT = 256;  // threads per CTA

__device__ __forceinline__ bool mask_at(const void* m, long idx, int kind)
{
    if (kind == 1) return ((const int*)m)[idx] != 0;
    if (kind == 2) return ((const float*)m)[idx] != 0.f;
    return ((const unsigned char*)m)[idx] != 0;
}

__device__ __forceinline__ float fast_tanh(float x)
{
    float y;
    asm("tanh.approx.f32 %0, %1;" : "=f"(y) : "f"(x));
    return y;
}

__global__ __launch_bounds__(NT)
void enc_kernel(const int* __restrict__ nodes,
                const int* __restrict__ hist_u,
                const int* __restrict__ hist_r,
                const void* __restrict__ hist_m,
                const int* __restrict__ soc_a,
                const void* __restrict__ soc_m,
                const float* __restrict__ features,
                const float* __restrict__ r_embed,
                const float* __restrict__ wg1,
                const float* __restrict__ bg1,
                const float* __restrict__ wg2,
                const float* __restrict__ bg2,
                const float* __restrict__ w1,
                const float* __restrict__ b1,
                float* __restrict__ out)
{
    __shared__ __align__(16) float4 s_mem4[R][G][D / 4];   // member embeddings (8 KB)
    __shared__ __align__(16) float  s_wg1T[A][68];          // wg1 transposed, padded (4.25 KB)
    __shared__ __align__(16) float  s_comb[R][2 * D];       // [self | neigh] (2 KB)
    __shared__ __align__(16) float4 s_red[8][R][D / 4];     // reduction scratch (8 KB, reused)
    __shared__ float s_lg[2][R][G];
    __shared__ int   s_hu[R][L];
    __shared__ int   s_su[R][S];
    __shared__ int   s_hn[R], s_sn[R], s_rcnt[R][NR];
    __shared__ unsigned int s_flags[2];

    const int tid = threadIdx.x;
    const int b0  = blockIdx.x * R;
    const int r   = tid >> 6;
    const int t   = tid & 63;

    // ---------- P0: zero counters/flags ----------
    if (tid < R)       { s_hn[tid] = 0; s_sn[tid] = 0; }
    if (tid < 2)       s_flags[tid] = 0u;
    if (tid < R * NR)  s_rcnt[tid / NR][tid % NR] = 0;
    __syncthreads();

    // ---------- P1: mask dtype detection + stage members + stage wg1T ----------
    // Detect from the first 64 words of history_mask (same for all CTAs, deterministic).
    {
        unsigned int v = (tid < 64) ? ((const unsigned int*)hist_m)[tid] : 0u;
        if (v > 1u)                        atomicOr(&s_flags[0], 1u);
        if (v != 0u && v != 0x3F800000u)   atomicOr(&s_flags[1], 1u);
    }
    // member embeddings: R*G rows of 16 float4
    for (int i = tid; i < R * G * (D / 4); i += NT) {
        int rr = i >> 7, g = (i >> 4) & 7, d4 = i & 15;
        int u = nodes[(b0 + rr) * G + g];
        s_mem4[rr][g][d4] = ((const float4*)features)[u * (D / 4) + d4];
    }
    // wg1 [64][16] -> transposed [16][68-padded]
    for (int i = tid; i < D * A; i += NT) {
        int dd = i >> 4, a = i & 15;
        s_wg1T[a][dd] = wg1[i];
    }
    __syncthreads();

    const int kind = (!s_flags[0]) ? 1 : ((!s_flags[1]) ? 2 : 0);

    // ---------- P2: mask compaction + rating histogram + attention logits ----------
    // compaction (R*L = 200 <= 256, R*S = 128 <= 256)
    if (tid < R * L) {
        int rr = tid / L, j = tid - rr * L;
        long gi = (long)(b0 + rr) * L + j;
        if (mask_at(hist_m, gi, kind)) {
            int p = atomicAdd(&s_hn[rr], 1);
            s_hu[rr][p] = hist_u[gi];
            atomicAdd(&s_rcnt[rr][hist_r[gi]], 1);
        }
    }
    if (tid < R * S) {
        int rr = tid >> 5, j = tid & 31;
        long gi = (long)(b0 + rr) * S + j;
        if (mask_at(soc_m, gi, kind)) {
            int p = atomicAdd(&s_sn[rr], 1);
            s_su[rr][p] = soc_a[gi];
        }
    }
    // attention: thread = (r, a = t>>2, dchunk = t&3); wg1T column in 16 regs
    {
        const int a = t >> 2, dc = t & 3;
        float wg1r[16];
        {
            float4* wr = (float4*)wg1r;
            #pragma unroll
            for (int i = 0; i < 4; ++i)
                wr[i] = *(const float4*)&s_wg1T[a][dc * 16 + 4 * i];
        }
        const float bg1a = bg1[a];
        const float wg2a = wg2[a];
        #pragma unroll
        for (int g = 0; g < G; ++g) {
            float p = 0.f;
            #pragma unroll
            for (int i = 0; i < 4; ++i) {
                float4 mv = s_mem4[r][g][dc * 4 + i];
                p += mv.x * wg1r[4 * i]     + mv.y * wg1r[4 * i + 1]
                   + mv.z * wg1r[4 * i + 2] + mv.w * wg1r[4 * i + 3];
            }
            // reduce over dchunk (lane bits 0..1)
            p += __shfl_xor_sync(0xffffffffu, p, 1);
            p += __shfl_xor_sync(0xffffffffu, p, 2);
            float lg = fast_tanh(p + bg1a) * wg2a;
            // reduce over a within warp (lane bits 2..4)
            lg += __shfl_xor_sync(0xffffffffu, lg, 4);
            lg += __shfl_xor_sync(0xffffffffu, lg, 8);
            lg += __shfl_xor_sync(0xffffffffu, lg, 16);
            if ((tid & 31) == 0)
                s_lg[(tid >> 5) & 1][r][g] = lg;
        }
    }
    __syncthreads();

    // ---------- P3: softmax + self_feats (thread = (r,d)) and gathers (thread = (r,e,d4)) ----------
    {
        const int d = t;
        const float bg2v = bg2[0];
        float lgv[G];
        #pragma unroll
        for (int g = 0; g < G; ++g)
            lgv[g] = s_lg[0][r][g] + s_lg[1][r][g] + bg2v;
        float mx = lgv[0];
        #pragma unroll
        for (int g = 1; g < G; ++g) mx = fmaxf(mx, lgv[g]);
        float sum = 0.f;
        #pragma unroll
        for (int g = 0; g < G; ++g) { lgv[g] = __expf(lgv[g] - mx); sum += lgv[g]; }
        const float inv = 1.f / sum;
        float sf = 0.f;
        #pragma unroll
        for (int g = 0; g < G; ++g)
            sf += lgv[g] * ((const float*)&s_mem4[r][g][0])[d];
        s_comb[r][d] = sf * inv;
    }
    {
        const int e = t >> 4, d4 = t & 15;
        const float4* f4 = (const float4*)features;
        float4 ha = make_float4(0.f, 0.f, 0.f, 0.f);
        const int hn = s_hn[r];
        #pragma unroll 2
        for (int l = e; l < hn; l += 4) {
            int u = s_hu[r][l];
            float4 fv = f4[u * (D / 4) + d4];
            ha.x += fv.x; ha.y += fv.y; ha.z += fv.z; ha.w += fv.w;
        }
        s_red[e][r][d4] = ha;
        float4 sa = make_float4(0.f, 0.f, 0.f, 0.f);
        const int sn = s_sn[r];
        #pragma unroll 2
        for (int l = e; l < sn; l += 4) {
            int u = s_su[r][l];
            float4 fv = f4[u * (D / 4) + d4];
            sa.x += fv.x; sa.y += fv.y; sa.z += fv.z; sa.w += fv.w;
        }
        s_red[4 + e][r][d4] = sa;
    }
    __syncthreads();

    // ---------- P4: neighbor combine (thread = (r,d)) ----------
    {
        const int d = t;
        const float* rf = (const float*)s_red;
        float hs = 0.f, ss = 0.f;
        #pragma unroll
        for (int e = 0; e < 4; ++e) {
            hs += rf[((e)     * R + r) * D + d];
            ss += rf[((4 + e) * R + r) * D + d];
        }
        // rating histogram * r_embed (linearity of masked sum)
        #pragma unroll
        for (int rt = 0; rt < NR; ++rt)
            hs += (float)s_rcnt[r][rt] * r_embed[rt * D + d];
        float hm = hs / fmaxf((float)s_hn[r], 1.f);
        float sm = ss / fmaxf((float)s_sn[r], 1.f);
        s_comb[r][D + d] = 0.5f * (hm + sm);
    }
    __syncthreads();

    // ---------- P5: final GEMM, k-split across 8 warps (w1 read once per CTA) ----------
    {
        const int w    = tid >> 5;
        const int lane = tid & 31;
        const int d4g  = lane & 15;
        const int kh   = lane >> 4;
        const float4* w1v = (const float4*)w1;
        float4 acc[R];
        #pragma unroll
        for (int rr = 0; rr < R; ++rr) acc[rr] = make_float4(0.f, 0.f, 0.f, 0.f);
        #pragma unroll
        for (int i = 0; i < 8; ++i) {
            const int k = 16 * w + 8 * kh + i;
            float4 wv = w1v[k * (D / 4) + d4g];
            #pragma unroll
            for (int rr = 0; rr < R; ++rr) {
                float c = s_comb[rr][k];
                acc[rr].x += c * wv.x; acc[rr].y += c * wv.y;
                acc[rr].z += c * wv.z; acc[rr].w += c * wv.w;
            }
        }
        // combine kh halves via shuffle
        #pragma unroll
        for (int rr = 0; rr < R; ++rr) {
            acc[rr].x += __shfl_xor_sync(0xffffffffu, acc[rr].x, 16);
            acc[rr].y += __shfl_xor_sync(0xffffffffu, acc[rr].y, 16);
            acc[rr].z += __shfl_xor_sync(0xffffffffu, acc[rr].z, 16);
            acc[rr].w += __shfl_xor_sync(0xffffffffu, acc[rr].w, 16);
        }
        if (kh == 0) {
            #pragma unroll
            for (int rr = 0; rr < R; ++rr)
                s_red[w][rr][d4g] = acc[rr];
        }
    }
    __syncthreads();

    // ---------- P6: reduce over 8 k-slices + bias + relu + store ----------
    {
        const int d = t;
        const float* rf = (const float*)s_red;
        float o = b1[d];
        #pragma unroll
        for (int w2 = 0; w2 < 8; ++w2)
            o += rf[(w2 * R + r) * D + d];
        out[(long)(b0 + r) * D + d] = fmaxf(o, 0.f);
    }
}

} // namespace

extern "C" void kernel_launch(void* const* d_in, const int* in_sizes, int n_in,
                              void* d_out, int out_size)
{
    const int*   nodes    = (const int*)d_in[0];
    const int*   hist_u   = (const int*)d_in[1];
    const int*   hist_r   = (const int*)d_in[2];
    const void*  hist_m   = d_in[3];
    const int*   soc_a    = (const int*)d_in[4];
    const void*  soc_m    = d_in[5];
    const float* features = (const float*)d_in[6];
    const float* r_embed  = (const float*)d_in[7];
    const float* wg1      = (const float*)d_in[8];
    const float* bg1      = (const float*)d_in[9];
    const float* wg2      = (const float*)d_in[10];
    const float* bg2      = (const float*)d_in[11];
    const float* w1       = (const float*)d_in[12];
    const float* b1       = (const float*)d_in[13];
    float*       out      = (float*)d_out;

    const int B = in_sizes[0] / G;

    enc_kernel<<<B / R, NT>>>(nodes, hist_u, hist_r, hist_m, soc_a, soc_m,
                              features, r_embed, wg1, bg1, wg2, bg2, w1, b1, out);
}

// round 4
// speedup vs baseline: 1.2331x; 1.0490x over previous
#include <cuda_runtime.h>

namespace {

constexpr int G  = 8;    // group size
constexpr int L  = 50;   // history length
constexpr int S  = 32;   // social neighbors
constexpr int D  = 64;   // embed dim
constexpr int A  = 16;   // attention dim
constexpr int NR = 5;    // num ratings
constexpr int R  = 4;    // batch rows per CTA
constexpr int NT = 256;  // threads per CTA

__device__ __forceinline__ bool mask_at(const void* m, long idx, int kind)
{
    if (kind == 1) return ((const int*)m)[idx] != 0;
    if (kind == 2) return ((const float*)m)[idx] != 0.f;
    return ((const unsigned char*)m)[idx] != 0;
}

__device__ __forceinline__ float fast_tanh(float x)
{
    float y;
    asm("tanh.approx.f32 %0, %1;" : "=f"(y) : "f"(x));
    return y;
}

__global__ __launch_bounds__(NT, 6)
void enc_kernel(const int* __restrict__ nodes,
                const int* __restrict__ hist_u,
                const int* __restrict__ hist_r,
                const void* __restrict__ hist_m,
                const int* __restrict__ soc_a,
                const void* __restrict__ soc_m,
                const float* __restrict__ features,
                const float* __restrict__ r_embed,
                const float* __restrict__ wg1,
                const float* __restrict__ bg1,
                const float* __restrict__ wg2,
                const float* __restrict__ bg2,
                const float* __restrict__ w1,
                const float* __restrict__ b1,
                float* __restrict__ out)
{
    __shared__ __align__(16) float4 s_mem4[R][G][D / 4];   // member embeddings (8 KB)
    __shared__ __align__(16) float  s_wg1T[A][68];          // wg1 transposed, padded (4.25 KB)
    __shared__ __align__(16) float  s_comb[R][2 * D];       // [self | neigh] (2 KB)
    __shared__ __align__(16) float4 s_red[8][R][D / 4];     // reduction scratch (8 KB, reused)
    __shared__ float s_lg[2][R][G];
    __shared__ int   s_hu[R][L];
    __shared__ int   s_su[R][S];
    __shared__ int   s_hn[R], s_sn[R], s_rcnt[R][NR];
    __shared__ unsigned int s_flags[2];

    const int tid = threadIdx.x;
    const int b0  = blockIdx.x * R;
    const int r   = tid >> 6;
    const int t   = tid & 63;

    // ---------- P0: zero counters/flags ----------
    if (tid < R)       { s_hn[tid] = 0; s_sn[tid] = 0; }
    if (tid < 2)       s_flags[tid] = 0u;
    if (tid < R * NR)  s_rcnt[tid / NR][tid % NR] = 0;
    __syncthreads();

    // ---------- P1: mask dtype detection + stage members + stage wg1T ----------
    {
        unsigned int v = (tid < 64) ? ((const unsigned int*)hist_m)[tid] : 0u;
        if (v > 1u)                        atomicOr(&s_flags[0], 1u);
        if (v != 0u && v != 0x3F800000u)   atomicOr(&s_flags[1], 1u);
    }
    for (int i = tid; i < R * G * (D / 4); i += NT) {
        int rr = i >> 7, g = (i >> 4) & 7, d4 = i & 15;
        int u = nodes[(b0 + rr) * G + g];
        s_mem4[rr][g][d4] = ((const float4*)features)[u * (D / 4) + d4];
    }
    for (int i = tid; i < D * A; i += NT) {
        int dd = i >> 4, a = i & 15;
        s_wg1T[a][dd] = wg1[i];
    }
    __syncthreads();

    const int kind = (!s_flags[0]) ? 1 : ((!s_flags[1]) ? 2 : 0);

    // ---------- P2: mask compaction + rating histogram + attention logits ----------
    if (tid < R * L) {
        int rr = tid / L, j = tid - rr * L;
        long gi = (long)(b0 + rr) * L + j;
        if (mask_at(hist_m, gi, kind)) {
            int p = atomicAdd(&s_hn[rr], 1);
            s_hu[rr][p] = hist_u[gi];
            atomicAdd(&s_rcnt[rr][hist_r[gi]], 1);
        }
    }
    if (tid < R * S) {
        int rr = tid >> 5, j = tid & 31;
        long gi = (long)(b0 + rr) * S + j;
        if (mask_at(soc_m, gi, kind)) {
            int p = atomicAdd(&s_sn[rr], 1);
            s_su[rr][p] = soc_a[gi];
        }
    }
    // attention: thread = (r, a = t>>2, dchunk = t&3)
    {
        const int a = t >> 2, dc = t & 3;
        float wg1r[16];
        {
            float4* wr = (float4*)wg1r;
            #pragma unroll
            for (int i = 0; i < 4; ++i)
                wr[i] = *(const float4*)&s_wg1T[a][dc * 16 + 4 * i];
        }
        const float bg1a = bg1[a];
        const float wg2a = wg2[a];
        #pragma unroll
        for (int g = 0; g < G; ++g) {
            float p = 0.f;
            #pragma unroll
            for (int i = 0; i < 4; ++i) {
                float4 mv = s_mem4[r][g][dc * 4 + i];
                p += mv.x * wg1r[4 * i]     + mv.y * wg1r[4 * i + 1]
                   + mv.z * wg1r[4 * i + 2] + mv.w * wg1r[4 * i + 3];
            }
            p += __shfl_xor_sync(0xffffffffu, p, 1);
            p += __shfl_xor_sync(0xffffffffu, p, 2);
            float lg = fast_tanh(p + bg1a) * wg2a;
            lg += __shfl_xor_sync(0xffffffffu, lg, 4);
            lg += __shfl_xor_sync(0xffffffffu, lg, 8);
            lg += __shfl_xor_sync(0xffffffffu, lg, 16);
            if ((tid & 31) == 0)
                s_lg[(tid >> 5) & 1][r][g] = lg;
        }
    }
    __syncthreads();

    // ---------- P3: softmax + self_feats (thread = (r,d)) and gathers (thread = (r,e,d4)) ----------
    {
        const int d = t;
        const float bg2v = bg2[0];
        float lgv[G];
        #pragma unroll
        for (int g = 0; g < G; ++g)
            lgv[g] = s_lg[0][r][g] + s_lg[1][r][g] + bg2v;
        float mx = lgv[0];
        #pragma unroll
        for (int g = 1; g < G; ++g) mx = fmaxf(mx, lgv[g]);
        float sum = 0.f;
        #pragma unroll
        for (int g = 0; g < G; ++g) { lgv[g] = __expf(lgv[g] - mx); sum += lgv[g]; }
        const float inv = 1.f / sum;
        float sf = 0.f;
        #pragma unroll
        for (int g = 0; g < G; ++g)
            sf += lgv[g] * ((const float*)&s_mem4[r][g][0])[d];
        s_comb[r][d] = sf * inv;
    }
    {
        const int e = t >> 4, d4 = t & 15;
        const float4* f4 = (const float4*)features;
        float4 ha = make_float4(0.f, 0.f, 0.f, 0.f);
        const int hn = s_hn[r];
        #pragma unroll 2
        for (int l = e; l < hn; l += 4) {
            int u = s_hu[r][l];
            float4 fv = f4[u * (D / 4) + d4];
            ha.x += fv.x; ha.y += fv.y; ha.z += fv.z; ha.w += fv.w;
        }
        s_red[e][r][d4] = ha;
        float4 sa = make_float4(0.f, 0.f, 0.f, 0.f);
        const int sn = s_sn[r];
        #pragma unroll 2
        for (int l = e; l < sn; l += 4) {
            int u = s_su[r][l];
            float4 fv = f4[u * (D / 4) + d4];
            sa.x += fv.x; sa.y += fv.y; sa.z += fv.z; sa.w += fv.w;
        }
        s_red[4 + e][r][d4] = sa;
    }
    __syncthreads();

    // ---------- P4: neighbor combine (thread = (r,d)) ----------
    {
        const int d = t;
        const float* rf = (const float*)s_red;
        float hs = 0.f, ss = 0.f;
        #pragma unroll
        for (int e = 0; e < 4; ++e) {
            hs += rf[((e)     * R + r) * D + d];
            ss += rf[((4 + e) * R + r) * D + d];
        }
        #pragma unroll
        for (int rt = 0; rt < NR; ++rt)
            hs += (float)s_rcnt[r][rt] * r_embed[rt * D + d];
        float hm = hs / fmaxf((float)s_hn[r], 1.f);
        float sm = ss / fmaxf((float)s_sn[r], 1.f);
        s_comb[r][D + d] = 0.5f * (hm + sm);
    }
    __syncthreads();

    // ---------- P5: final GEMM, k-split across 8 warps; half-warp = 2 rows ----------
    {
        const int w    = tid >> 5;           // k-slice: k in [16w, 16w+16)
        const int lane = tid & 31;
        const int d4g  = lane & 15;
        const int rh   = lane >> 4;          // row-half: rows {2rh, 2rh+1}
        const float4* w1v = (const float4*)w1;
        float4 a0 = make_float4(0.f, 0.f, 0.f, 0.f);
        float4 a1 = make_float4(0.f, 0.f, 0.f, 0.f);
        #pragma unroll
        for (int i = 0; i < 16; ++i) {
            const int k = 16 * w + i;
            float4 wv = w1v[k * (D / 4) + d4g];
            float c0 = s_comb[2 * rh][k];
            float c1 = s_comb[2 * rh + 1][k];
            a0.x += c0 * wv.x; a0.y += c0 * wv.y; a0.z += c0 * wv.z; a0.w += c0 * wv.w;
            a1.x += c1 * wv.x; a1.y += c1 * wv.y; a1.z += c1 * wv.z; a1.w += c1 * wv.w;
        }
        s_red[w][2 * rh][d4g]     = a0;
        s_red[w][2 * rh + 1][d4g] = a1;
    }
    __syncthreads();

    // ---------- P6: reduce over 8 k-slices + bias + relu + store ----------
    {
        const int d = t;
        const float* rf = (const float*)s_red;
        float o = b1[d];
        #pragma unroll
        for (int w2 = 0; w2 < 8; ++w2)
            o += rf[(w2 * R + r) * D + d];
        out[(long)(b0 + r) * D + d] = fmaxf(o, 0.f);
    }
}

} // namespace

extern "C" void kernel_launch(void* const* d_in, const int* in_sizes, int n_in,
                              void* d_out, int out_size)
{
    const int*   nodes    = (const int*)d_in[0];
    const int*   hist_u   = (const int*)d_in[1];
    const int*   hist_r   = (const int*)d_in[2];
    const void*  hist_m   = d_in[3];
    const int*   soc_a    = (const int*)d_in[4];
    const void*  soc_m    = d_in[5];
    const float* features = (const float*)d_in[6];
    const float* r_embed  = (const float*)d_in[7];
    const float* wg1      = (const float*)d_in[8];
    const float* bg1      = (const float*)d_in[9];
    const float* wg2      = (const float*)d_in[10];
    const float* bg2      = (const float*)d_in[11];
    const float* w1       = (const float*)d_in[12];
    const float* b1       = (const float*)d_in[13];
    float*       out      = (float*)d_out;

    const int B = in_sizes[0] / G;

    enc_kernel<<<B / R, NT>>>(nodes, hist_u, hist_r, hist_m, soc_a, soc_m,
                              features, r_embed, wg1, bg1, wg2, bg2, w1, b1, out);
}